// round 2
// baseline (speedup 1.0000x reference)
#include <cuda_runtime.h>
#include <cuda_bf16.h>

// loss = sum_{b,c,s,h,w} (out[b,c,2s,h,w] - target[b,c,2s+1,h,w])^2 / (C*H*Wd * W/2)
// B=8, C=32, W=16 (s=0..7), H=128, Wd=128.
//
// Used elements per tensor: N = 8*32*8*16384 = 33,554,432  (N4 = 8,388,608 float4)
// float4 index e4: g = e4>>12, hw4 = e4&4095
//   out4 = (g<<13) + hw4 ; tgt4 = out4 + 4096
//
// Single launch: grid-stride partial sums -> last-block-done final reduction.

#define NBLOCKS 2048
#define NTHREADS 256

__device__ float g_partials[NBLOCKS];
__device__ unsigned int g_count = 0;   // reset by last block each launch -> graph-replay safe

__global__ __launch_bounds__(NTHREADS) void cont_loss_fused_kernel(
    const float4* __restrict__ out4, const float4* __restrict__ tgt4,
    float* __restrict__ result)
{
    const long long N4 = 8388608LL;
    long long stride = (long long)gridDim.x * blockDim.x;
    long long i = (long long)blockIdx.x * blockDim.x + threadIdx.x;

    float acc = 0.0f;
    #pragma unroll 4
    for (; i < N4; i += stride) {
        long long g   = i >> 12;
        long long hw4 = i & 4095;
        long long oa  = (g << 13) + hw4;
        float4 o = out4[oa];
        float4 t = tgt4[oa + 4096];
        float d0 = o.x - t.x;
        float d1 = o.y - t.y;
        float d2 = o.z - t.z;
        float d3 = o.w - t.w;
        acc = fmaf(d0, d0, acc);
        acc = fmaf(d1, d1, acc);
        acc = fmaf(d2, d2, acc);
        acc = fmaf(d3, d3, acc);
    }

    // deterministic block reduction
    __shared__ float sbuf[NTHREADS];
    sbuf[threadIdx.x] = acc;
    __syncthreads();
    #pragma unroll
    for (int ofs = NTHREADS / 2; ofs > 0; ofs >>= 1) {
        if (threadIdx.x < ofs) sbuf[threadIdx.x] += sbuf[threadIdx.x + ofs];
        __syncthreads();
    }

    __shared__ bool s_is_last;
    if (threadIdx.x == 0) {
        g_partials[blockIdx.x] = sbuf[0];
        __threadfence();  // partial visible before counter bump
        unsigned int prev = atomicAdd(&g_count, 1u);
        s_is_last = (prev == (unsigned int)(gridDim.x - 1));
    }
    __syncthreads();

    if (s_is_last) {
        // Last block: sum all partials in double, scale, write, reset counter.
        __shared__ double dbuf[NTHREADS];
        double dacc = 0.0;
        for (int k = threadIdx.x; k < NBLOCKS; k += NTHREADS)
            dacc += (double)g_partials[k];
        dbuf[threadIdx.x] = dacc;
        __syncthreads();
        #pragma unroll
        for (int ofs = NTHREADS / 2; ofs > 0; ofs >>= 1) {
            if (threadIdx.x < ofs) dbuf[threadIdx.x] += dbuf[threadIdx.x + ofs];
            __syncthreads();
        }
        if (threadIdx.x == 0) {
            const double scale = 1.0 / (524288.0 * 8.0);  // mean(C,H,Wd) then /half_win
            result[0] = (float)(dbuf[0] * scale);
            g_count = 0;  // re-arm for next graph replay
        }
    }
}

extern "C" void kernel_launch(void* const* d_in, const int* in_sizes, int n_in,
                              void* d_out, int out_size)
{
    const float4* out4 = (const float4*)d_in[0];
    const float4* tgt4 = (const float4*)d_in[1];
    float* o = (float*)d_out;

    cont_loss_fused_kernel<<<NBLOCKS, NTHREADS>>>(out4, tgt4, o);
}

// round 3
// speedup vs baseline: 1.0744x; 1.0744x over previous
#include <cuda_runtime.h>
#include <cuda_bf16.h>

// loss = sum_{b,c,s,h,w} (out[b,c,2s,h,w] - target[b,c,2s+1,h,w])^2 / (C*H*Wd * W/2)
// B=8, C=32, W=16 (s=0..7), H=128, Wd=128.
//
// 2048 slabs (g = flattened b,c,s). Slab g:
//   out float4 base : out4 + (g<<13)          (4096 float4 = 64 KB)
//   tgt float4 base : tgt4 + (g<<13) + 4096   (4096 float4 = 64 KB)
// One CTA per slab, 256 threads x 16 float4 pairs, stride 256, fully unrolled.

#define NBLOCKS 2048
#define NTHREADS 256
#define PER_THREAD 16   // 4096 / 256

__device__ float g_partials[NBLOCKS];
__device__ unsigned int g_count = 0;   // reset by last block -> graph-replay safe

__global__ __launch_bounds__(NTHREADS) void cont_loss_fused_kernel(
    const float4* __restrict__ out4, const float4* __restrict__ tgt4,
    float* __restrict__ result)
{
    const long long base = ((long long)blockIdx.x << 13);
    const float4* __restrict__ op = out4 + base + threadIdx.x;
    const float4* __restrict__ tp = tgt4 + base + 4096 + threadIdx.x;

    float a0 = 0.0f, a1 = 0.0f, a2 = 0.0f, a3 = 0.0f;
    #pragma unroll
    for (int k = 0; k < PER_THREAD; k++) {
        float4 o = op[k * NTHREADS];
        float4 t = tp[k * NTHREADS];
        float d0 = o.x - t.x;
        float d1 = o.y - t.y;
        float d2 = o.z - t.z;
        float d3 = o.w - t.w;
        a0 = fmaf(d0, d0, a0);
        a1 = fmaf(d1, d1, a1);
        a2 = fmaf(d2, d2, a2);
        a3 = fmaf(d3, d3, a3);
    }
    float acc = (a0 + a1) + (a2 + a3);

    // deterministic block reduction
    __shared__ float sbuf[NTHREADS];
    sbuf[threadIdx.x] = acc;
    __syncthreads();
    #pragma unroll
    for (int ofs = NTHREADS / 2; ofs > 0; ofs >>= 1) {
        if (threadIdx.x < ofs) sbuf[threadIdx.x] += sbuf[threadIdx.x + ofs];
        __syncthreads();
    }

    __shared__ bool s_is_last;
    if (threadIdx.x == 0) {
        g_partials[blockIdx.x] = sbuf[0];
        __threadfence();  // partial visible before counter bump
        unsigned int prev = atomicAdd(&g_count, 1u);
        s_is_last = (prev == (unsigned int)(gridDim.x - 1));
    }
    __syncthreads();

    if (s_is_last) {
        // Sum all 2048 partials in double, scale, write, re-arm counter.
        __shared__ double dbuf[NTHREADS];
        double dacc = 0.0;
        #pragma unroll
        for (int k = 0; k < NBLOCKS / NTHREADS; k++)
            dacc += (double)g_partials[threadIdx.x + k * NTHREADS];
        dbuf[threadIdx.x] = dacc;
        __syncthreads();
        #pragma unroll
        for (int ofs = NTHREADS / 2; ofs > 0; ofs >>= 1) {
            if (threadIdx.x < ofs) dbuf[threadIdx.x] += dbuf[threadIdx.x + ofs];
            __syncthreads();
        }
        if (threadIdx.x == 0) {
            const double scale = 1.0 / (524288.0 * 8.0);  // mean(C,H,Wd) then /half_win
            result[0] = (float)(dbuf[0] * scale);
            g_count = 0;
        }
    }
}

extern "C" void kernel_launch(void* const* d_in, const int* in_sizes, int n_in,
                              void* d_out, int out_size)
{
    const float4* out4 = (const float4*)d_in[0];
    const float4* tgt4 = (const float4*)d_in[1];
    float* o = (float*)d_out;

    cont_loss_fused_kernel<<<NBLOCKS, NTHREADS>>>(out4, tgt4, o);
}